// round 14
// baseline (speedup 1.0000x reference)
#include <cuda_runtime.h>
#include <cstdint>

#define DD 8
#define BB 8
#define NN 2048
#define NN2 (NN * NN)        // 4194304

// 64-bit spike mask per presynaptic neuron e: bit (d*8+b) set iff Xd[d,b,e]==1
__device__ unsigned long long g_spike[NN];

// ---------------------------------------------------------------------------
// Kernel 1: ballot-pack spike masks (one warp per e) + zero output.
// ---------------------------------------------------------------------------
__global__ void __launch_bounds__(256)
pack_kernel(const float* __restrict__ Xd, float* __restrict__ out) {
    const int gid  = blockIdx.x * 256 + threadIdx.x;
    const int lane = threadIdx.x & 31;
    const int e    = gid >> 5;                       // global warp id = e

    const bool s0 = Xd[(size_t)lane        * NN + e] > 0.5f;
    const bool s1 = Xd[(size_t)(lane + 32) * NN + e] > 0.5f;
    const unsigned lo = __ballot_sync(0xFFFFFFFFu, s0);
    const unsigned hi = __ballot_sync(0xFFFFFFFFu, s1);
    if (lane == 0)
        g_spike[e] = (unsigned long long)lo | ((unsigned long long)hi << 32);

    if (gid < BB * NN) out[gid] = 0.0f;
}

// ---------------------------------------------------------------------------
// Kernel 2: fused gate + blend + reduce over 32e x 128o tiles.
//   Phase A1 (warp -> 4 e-rows): spike-gated delaymap read (~2.7/8 planes)
//     -> packed gate words in smem + per-(warp,batch) 4-bit row-activity
//     nibble (register-computed, no atomics).
//   Phase A2: statics float4 streams -> cs/cp in smem.
//   Phase B (warp = batch b, lane = o-quad): build 32-bit active-row mask
//     (~16 ops), then while(mask){ffs} over ~10.8 active rows. Tight body:
//     1 LDS.32 gate + 2 LDS.128 coeff + 1 LDG.128 Wlong + 4 pred. FMAs.
//     No per-row branches; loads batch across iterations.
// ---------------------------------------------------------------------------
#define ET 32
#define OT 128

__global__ void __launch_bounds__(256)
fused_kernel(const float4* __restrict__ dm4,   // delaymap (D,N,N)
             const float4* __restrict__ W4,    // (N,N)
             const float*  __restrict__ Wl,    // Wlong (B,N,N)
             const float4* __restrict__ F4,    // STDP_frac (N,N)
             const float4* __restrict__ S4,    // signs (N,N)
             float* __restrict__ out)          // (B,N)
{
    __shared__ float         sCS[ET][OT];       // 16 KB
    __shared__ float         sCP[ET][OT];       // 16 KB
    __shared__ unsigned      sG[ET][OT / 4];    // 4 KB packed gate words
    __shared__ unsigned char sNib[8][8];        // [warp][batch] row-activity nibble

    const int t     = threadIdx.x;
    const int lane  = t & 31;
    const int w     = t >> 5;
    const int obase = blockIdx.x * OT;
    const int ebase = blockIdx.y * ET;

    // ---- Phase A1: gates + activity nibbles; warp -> rows 4w..4w+3 ----
    unsigned ub[4];
#pragma unroll
    for (int r = 0; r < 4; r++) {
        const int el = w * 4 + r;
        const int e  = ebase + el;
        const unsigned long long bits = g_spike[e];   // uniform (L2-resident)
        unsigned g0 = 0, g1 = 0, g2 = 0, g3 = 0;
#pragma unroll
        for (int d = 0; d < DD; d++) {
            const unsigned m8 = (unsigned)(bits >> (d * 8)) & 0xFFu;
            if (m8) {                                 // warp-uniform branch
                const float4 v =
                    dm4[((size_t)d * NN + e) * (NN / 4) + obase / 4 + lane];
                if (v.x > 0.5f) g0 = m8;              // one-hot: <=1 match
                if (v.y > 0.5f) g1 = m8;
                if (v.z > 0.5f) g2 = m8;
                if (v.w > 0.5f) g3 = m8;
            }
        }
        sG[el][lane] = g0 | (g1 << 8) | (g2 << 16) | (g3 << 24);
        unsigned long long u = bits | (bits >> 32);   // fold to 8-bit batch union
        u |= u >> 16;
        u |= u >> 8;
        ub[r] = (unsigned)u & 0xFFu;
    }
    if (lane < 8) {                                   // lane = batch
        const unsigned nib = ((ub[0] >> lane) & 1u)
                           | (((ub[1] >> lane) & 1u) << 1)
                           | (((ub[2] >> lane) & 1u) << 2)
                           | (((ub[3] >> lane) & 1u) << 3);
        sNib[w][lane] = (unsigned char)nib;
    }

    // ---- Phase A2: statics -> cs/cp (1024 float4 per array, 4 per thread) ----
#pragma unroll
    for (int k = 0; k < 4; k++) {
        const int idx = t + k * 256;                  // float4 index in tile
        const int ee  = idx >> 5;                     // 32 quads per row
        const int qq  = idx & 31;
        const size_t g4 = ((size_t)(ebase + ee) * NN + obase) / 4 + qq;
        const float4 s = S4[g4];
        const float4 wv = W4[g4];
        const float4 f = F4[g4];
        sCS[ee][qq * 4 + 0] = s.x * wv.x * (1.0f - f.x);
        sCS[ee][qq * 4 + 1] = s.y * wv.y * (1.0f - f.y);
        sCS[ee][qq * 4 + 2] = s.z * wv.z * (1.0f - f.z);
        sCS[ee][qq * 4 + 3] = s.w * wv.w * (1.0f - f.w);
        sCP[ee][qq * 4 + 0] = s.x * f.x;
        sCP[ee][qq * 4 + 1] = s.y * f.y;
        sCP[ee][qq * 4 + 2] = s.z * f.z;
        sCP[ee][qq * 4 + 3] = s.w * f.w;
    }
    __syncthreads();

    // ---- Phase B: warp = batch b; lane = o-quad; sparse ffs iteration ----
    const int b = w;
    unsigned mask = 0;
#pragma unroll
    for (int ww = 0; ww < 8; ww++)                    // broadcast LDS (no conflicts)
        mask |= (unsigned)sNib[ww][b] << (ww * 4);

    const float4* __restrict__ wlb = (const float4*)(Wl + (size_t)b * NN2)
                                   + ((size_t)ebase * NN + obase) / 4 + lane;

    float a0 = 0.f, a1 = 0.f, a2 = 0.f, a3 = 0.f;
    while (mask) {                                    // warp-uniform, ~10.8 iters
        const int ee = __ffs(mask) - 1;
        mask &= mask - 1;

        const unsigned gs = sG[ee][lane] >> b;        // bits 0/8/16/24 = gates
        const float4 wl = wlb[(size_t)ee * (NN / 4)]; // sole DRAM access
        const float4 cs = *(const float4*)&sCS[ee][lane * 4];
        const float4 cp = *(const float4*)&sCP[ee][lane * 4];
        a0 += (gs & 0x00000001u) ? fmaf(cp.x, wl.x, cs.x) : 0.0f;
        a1 += (gs & 0x00000100u) ? fmaf(cp.y, wl.y, cs.y) : 0.0f;
        a2 += (gs & 0x00010000u) ? fmaf(cp.z, wl.z, cs.z) : 0.0f;
        a3 += (gs & 0x01000000u) ? fmaf(cp.w, wl.w, cs.w) : 0.0f;
    }

    float* op = out + b * NN + obase + lane * 4;
    atomicAdd(op + 0, a0);
    atomicAdd(op + 1, a1);
    atomicAdd(op + 2, a2);
    atomicAdd(op + 3, a3);
}

// ---------------------------------------------------------------------------
// Launch
// ---------------------------------------------------------------------------
extern "C" void kernel_launch(void* const* d_in, const int* in_sizes, int n_in,
                              void* d_out, int out_size) {
    const float* Xd = (const float*)d_in[0];   // (D,B,N)
    const float* dm = (const float*)d_in[1];   // (D,N,N)
    const float* W  = (const float*)d_in[2];   // (N,N)
    const float* Wl = (const float*)d_in[3];   // (B,N,N)
    const float* F  = (const float*)d_in[4];   // (N,N)
    const float* S  = (const float*)d_in[5];   // (N,N)
    float* out = (float*)d_out;                // (B,N)

    pack_kernel<<<(NN * 32) / 256, 256>>>(Xd, out);   // 256 CTAs

    dim3 grid(NN / OT, NN / ET);                      // 16 x 64 = 1024 CTAs
    fused_kernel<<<grid, 256>>>((const float4*)dm, (const float4*)W, Wl,
                                (const float4*)F, (const float4*)S, out);
}

// round 15
// speedup vs baseline: 1.1484x; 1.1484x over previous
#include <cuda_runtime.h>
#include <cstdint>

#define DD 8
#define BB 8
#define NN 2048
#define NN2 (NN * NN)        // 4194304

// 64-bit spike mask per presynaptic neuron e: bit (d*8+b) set iff Xd[d,b,e]==1
__device__ unsigned long long g_spike[NN];

__device__ __forceinline__ unsigned smem_u32(const void* p) {
    return (unsigned)__cvta_generic_to_shared(p);
}

// ---------------------------------------------------------------------------
// Kernel 1: ballot-pack spike masks (one warp per e) + zero output.
// ---------------------------------------------------------------------------
__global__ void __launch_bounds__(256)
pack_kernel(const float* __restrict__ Xd, float* __restrict__ out) {
    const int gid  = blockIdx.x * 256 + threadIdx.x;
    const int lane = threadIdx.x & 31;
    const int e    = gid >> 5;                       // global warp id = e

    const bool s0 = Xd[(size_t)lane        * NN + e] > 0.5f;
    const bool s1 = Xd[(size_t)(lane + 32) * NN + e] > 0.5f;
    const unsigned lo = __ballot_sync(0xFFFFFFFFu, s0);
    const unsigned hi = __ballot_sync(0xFFFFFFFFu, s1);
    if (lane == 0)
        g_spike[e] = (unsigned long long)lo | ((unsigned long long)hi << 32);

    if (gid < BB * NN) out[gid] = 0.0f;
}

// ---------------------------------------------------------------------------
// Kernel 2: fused gate + blend + reduce over 16e x 128o tiles.
//   Order of operations engineered for stream overlap:
//     1. cp.async statics (S,W,F) global->smem: issued FIRST, no reg round-trip
//     2. Phase A1: spike-gated delaymap read (~2.7/8 planes) -> gate words
//        (overlaps with in-flight cp.async statics)
//     3. cp.async wait + barrier
//     4. Phase B (warp = batch b, lane = o-quad): uniform row-skip (P=0.663),
//        active rows: 3 LDS.128 + Wlong LDG.128 + inline blend FMAs.
// ---------------------------------------------------------------------------
#define ET 16
#define OT 128

__global__ void __launch_bounds__(256)
fused_kernel(const float4* __restrict__ dm4,   // delaymap (D,N,N)
             const float4* __restrict__ W4,    // (N,N)
             const float*  __restrict__ Wl,    // Wlong (B,N,N)
             const float4* __restrict__ F4,    // STDP_frac (N,N)
             const float4* __restrict__ S4,    // signs (N,N)
             float* __restrict__ out)          // (B,N)
{
    __shared__ float    sS[ET][OT];        // 8 KB
    __shared__ float    sW[ET][OT];        // 8 KB
    __shared__ float    sF[ET][OT];        // 8 KB
    __shared__ unsigned sG[ET][OT / 4];    // 2 KB packed gate words
    __shared__ unsigned sU[ET];            // per-row batch-union byte

    const int t     = threadIdx.x;
    const int lane  = t & 31;
    const int w     = t >> 5;
    const int obase = blockIdx.x * OT;
    const int ebase = blockIdx.y * ET;

    // ---- Step 1: cp.async raw statics (2 float4 per thread per array) ----
#pragma unroll
    for (int k = 0; k < 2; k++) {
        const int idx = t + k * 256;                  // float4 index in tile
        const int ee  = idx >> 5;                     // 32 quads per row
        const int qq  = idx & 31;
        const size_t g4 = ((size_t)(ebase + ee) * NN + obase) / 4 + qq;
        asm volatile("cp.async.cg.shared.global [%0], [%1], 16;\n"
                     :: "r"(smem_u32(&sS[ee][qq * 4])), "l"(S4 + g4));
        asm volatile("cp.async.cg.shared.global [%0], [%1], 16;\n"
                     :: "r"(smem_u32(&sW[ee][qq * 4])), "l"(W4 + g4));
        asm volatile("cp.async.cg.shared.global [%0], [%1], 16;\n"
                     :: "r"(smem_u32(&sF[ee][qq * 4])), "l"(F4 + g4));
    }
    asm volatile("cp.async.commit_group;\n");

    // ---- Step 2 (Phase A1): gates; warp -> rows 2w, 2w+1 ----
#pragma unroll
    for (int r = 0; r < 2; r++) {
        const int el = w * 2 + r;
        const int e  = ebase + el;
        const unsigned long long bits = g_spike[e];   // uniform (L2-resident)
        unsigned g0 = 0, g1 = 0, g2 = 0, g3 = 0;
#pragma unroll
        for (int d = 0; d < DD; d++) {
            const unsigned m8 = (unsigned)(bits >> (d * 8)) & 0xFFu;
            if (m8) {                                 // warp-uniform branch
                const float4 v =
                    dm4[((size_t)d * NN + e) * (NN / 4) + obase / 4 + lane];
                if (v.x > 0.5f) g0 = m8;              // one-hot: <=1 match
                if (v.y > 0.5f) g1 = m8;
                if (v.z > 0.5f) g2 = m8;
                if (v.w > 0.5f) g3 = m8;
            }
        }
        sG[el][lane] = g0 | (g1 << 8) | (g2 << 16) | (g3 << 24);
        if (lane == 0) {
            unsigned long long u = bits | (bits >> 32);
            u |= u >> 16;
            u |= u >> 8;
            sU[el] = (unsigned)u & 0xFFu;             // bit b: batch b spiked
        }
    }

    // ---- Step 3: wait for statics + make smem visible ----
    asm volatile("cp.async.wait_group 0;\n");
    __syncthreads();

    // ---- Step 4 (Phase B): warp = batch b; lane = o-quad; row-skip ----
    const int b = w;
    const float4* __restrict__ wlb = (const float4*)(Wl + (size_t)b * NN2)
                                   + ((size_t)ebase * NN + obase) / 4 + lane;

    float a0 = 0.f, a1 = 0.f, a2 = 0.f, a3 = 0.f;
#pragma unroll
    for (int ee = 0; ee < ET; ee++) {
        if (!((sU[ee] >> b) & 1u)) continue;          // warp-uniform skip (P=0.663)

        const unsigned gs = sG[ee][lane] >> b;        // bits 0/8/16/24 = gates
        const float4 wl = wlb[(size_t)ee * (NN / 4)]; // sole DRAM access
        const float4 sv = *(const float4*)&sS[ee][lane * 4];
        const float4 wv = *(const float4*)&sW[ee][lane * 4];
        const float4 fv = *(const float4*)&sF[ee][lane * 4];
        // s * (w*(1-f) + f*wl) = s * fma(f, wl - w, w)
        a0 += (gs & 0x00000001u) ? sv.x * fmaf(fv.x, wl.x - wv.x, wv.x) : 0.0f;
        a1 += (gs & 0x00000100u) ? sv.y * fmaf(fv.y, wl.y - wv.y, wv.y) : 0.0f;
        a2 += (gs & 0x00010000u) ? sv.z * fmaf(fv.z, wl.z - wv.z, wv.z) : 0.0f;
        a3 += (gs & 0x01000000u) ? sv.w * fmaf(fv.w, wl.w - wv.w, wv.w) : 0.0f;
    }

    float* op = out + b * NN + obase + lane * 4;
    atomicAdd(op + 0, a0);
    atomicAdd(op + 1, a1);
    atomicAdd(op + 2, a2);
    atomicAdd(op + 3, a3);
}

// ---------------------------------------------------------------------------
// Launch
// ---------------------------------------------------------------------------
extern "C" void kernel_launch(void* const* d_in, const int* in_sizes, int n_in,
                              void* d_out, int out_size) {
    const float* Xd = (const float*)d_in[0];   // (D,B,N)
    const float* dm = (const float*)d_in[1];   // (D,N,N)
    const float* W  = (const float*)d_in[2];   // (N,N)
    const float* Wl = (const float*)d_in[3];   // (B,N,N)
    const float* F  = (const float*)d_in[4];   // (N,N)
    const float* S  = (const float*)d_in[5];   // (N,N)
    float* out = (float*)d_out;                // (B,N)

    pack_kernel<<<(NN * 32) / 256, 256>>>(Xd, out);   // 256 CTAs

    dim3 grid(NN / OT, NN / ET);                      // 16 x 128 = 2048 CTAs
    fused_kernel<<<grid, 256>>>((const float4*)dm, (const float4*)W, Wl,
                                (const float4*)F, (const float4*)S, out);
}